// round 14
// baseline (speedup 1.0000x reference)
#include <cuda_runtime.h>
#include <math_constants.h>

// Bidirectional Chamfer distance, B=4, N=M=4096, D=3, fp32.
// dist[b,n,m] = |q_n|^2 + |t_m|^2 - 2 q_n.t_m  -- computed ONCE per (n,m),
// serving BOTH directions: row-mins in registers, col-mins via warp-butterfly
// pre-reduction (s_cand shrinks 33KB -> 1.25KB => 8 CTAs/SM => single wave).
// Margins merged via atomicMax on monotone keys (0 == +inf sentinel).
// K2: 8 blocks x 1024 thr decode+sum+reset keys, ticketed fixed-order final.

#define BATCH   4
#define NPTS    4096
#define THREADS 128
#define QPT     8
#define QBLK    (THREADS * QPT)          // 1024 queries per block
#define NQBLK   (NPTS / QBLK)            // 4
#define TT      64                       // targets per block
#define NTTILE  (NPTS / TT)              // 64
#define NKEY    (2 * BATCH * NPTS)       // 32768: [0,16384) rows, rest cols
#define COLBASE (BATCH * NPTS)           // 16384
#define NWARP   (THREADS / 32)           // 4
#define CSTRIDE (NWARP + 1)              // 5: conflict-free cand stride

#define R_THREADS 1024
#define R_NBLK    (NKEY / (4 * R_THREADS))   // 8 blocks, 1 uint4/thread

__device__ __align__(16) unsigned int g_key[NKEY];  // zero-init == +inf
__device__ float        g_bsum[R_NBLK];
__device__ unsigned int g_count;                    // zero-init; reset at end

// key(d) = ~f2key(d): monotone DECREASING in d; all finite d -> key > 0.
__device__ __forceinline__ unsigned int dkey(float f) {
    unsigned int u = __float_as_uint(f);
    unsigned int k = (u & 0x80000000u) ? ~u : (u | 0x80000000u);
    return ~k;
}
__device__ __forceinline__ float key2f(unsigned int kk) {
    unsigned int k = ~kk;
    unsigned int u = (k & 0x80000000u) ? (k & 0x7FFFFFFFu) : ~k;
    return __uint_as_float(u);
}

__global__ __launch_bounds__(THREADS, 8)
void chamfer_k1(const float* __restrict__ src,
                const float* __restrict__ tgt) {
    // sXY[t] = ((-2x,-2x),(-2y,-2y)), sZW[t] = ((-2z,-2z),(w,w)), w=|t|^2
    __shared__ ulonglong2 sXY[TT];
    __shared__ ulonglong2 sZW[TT];
    __shared__ float      s_cand[TT * CSTRIDE];  // [t][warp]

    const int qblk = blockIdx.x;
    const int tt   = blockIdx.y;
    const int b    = blockIdx.z;
    const int tid  = threadIdx.x;
    const int wid  = tid >> 5;
    const int lid  = tid & 31;

    const float* __restrict__ qb = src + (size_t)b * NPTS * 3;  // rows: source
    const float* __restrict__ tb = tgt + (size_t)b * NPTS * 3;  // cols: target

    // ---- load + duplicate-pack this block's 64 targets
    if (tid < TT) {
        int m = tt * TT + tid;
        float x = tb[m * 3 + 0], y = tb[m * 3 + 1], z = tb[m * 3 + 2];
        float w = fmaf(x, x, fmaf(y, y, z * z));
        float nx = -2.0f * x, ny = -2.0f * y, nz = -2.0f * z;
        unsigned long long px, py, pz, pw;
        asm("mov.b64 %0, {%1, %1};" : "=l"(px) : "f"(nx));
        asm("mov.b64 %0, {%1, %1};" : "=l"(py) : "f"(ny));
        asm("mov.b64 %0, {%1, %1};" : "=l"(pz) : "f"(nz));
        asm("mov.b64 %0, {%1, %1};" : "=l"(pw) : "f"(w));
        sXY[tid] = make_ulonglong2(px, py);
        sZW[tid] = make_ulonglong2(pz, pw);
    }

    // ---- load 8 queries/thread as 4 f32x2 pairs; |q|^2 packed as chain base
    const int q0 = qblk * QBLK + tid;
    unsigned long long qx2[4], qy2[4], qz2[4], q22[4];
    float rm[QPT];
#pragma unroll
    for (int r = 0; r < 4; r++) {
        int qa = q0 + (2 * r) * THREADS;
        int qc = qa + THREADS;
        float xa = qb[qa * 3 + 0], ya = qb[qa * 3 + 1], za = qb[qa * 3 + 2];
        float xc = qb[qc * 3 + 0], yc = qb[qc * 3 + 1], zc = qb[qc * 3 + 2];
        asm("mov.b64 %0, {%1, %2};" : "=l"(qx2[r]) : "f"(xa), "f"(xc));
        asm("mov.b64 %0, {%1, %2};" : "=l"(qy2[r]) : "f"(ya), "f"(yc));
        asm("mov.b64 %0, {%1, %2};" : "=l"(qz2[r]) : "f"(za), "f"(zc));
        float q2a = fmaf(xa, xa, fmaf(ya, ya, za * za));
        float q2c = fmaf(xc, xc, fmaf(yc, yc, zc * zc));
        asm("mov.b64 %0, {%1, %2};" : "=l"(q22[r]) : "f"(q2a), "f"(q2c));
        rm[2 * r] = CUDART_INF_F;
        rm[2 * r + 1] = CUDART_INF_F;
    }
    __syncthreads();

    // ---- main loop: per step (1 broadcast target x 8 queries):
    //      16 packed fma-ops + 15 FMNMX + 5 SHFL/FMNMX butterfly + 1 STS
#pragma unroll 4
    for (int t = 0; t < TT; t++) {
        ulonglong2 xy = sXY[t];   // .x=(-2x,-2x), .y=(-2y,-2y)
        ulonglong2 zw = sZW[t];   // .x=(-2z,-2z), .y=(w,w)
        float c[4];
#pragma unroll
        for (int r = 0; r < 4; r++) {
            float d0, d1;
            asm("{\n\t"
                ".reg .b64 d;\n\t"
                "fma.rn.f32x2 d, %2, %3, %4;\n\t"   // -2z*qz + |q|^2
                "fma.rn.f32x2 d, %5, %6, d;\n\t"    // -2y*qy
                "fma.rn.f32x2 d, %7, %8, d;\n\t"    // -2x*qx
                "add.rn.f32x2 d, d, %9;\n\t"        // + |t|^2
                "mov.b64 {%0, %1}, d;\n\t"
                "}"
                : "=f"(d0), "=f"(d1)
                : "l"(zw.x), "l"(qz2[r]), "l"(q22[r]),
                  "l"(xy.y), "l"(qy2[r]),
                  "l"(xy.x), "l"(qx2[r]),
                  "l"(zw.y));
            rm[2 * r]     = fminf(rm[2 * r], d0);
            rm[2 * r + 1] = fminf(rm[2 * r + 1], d1);
            c[r] = fminf(d0, d1);
        }
        // col candidate: min over this thread's 8 queries, then warp butterfly
        float cc = fminf(fminf(c[0], c[1]), fminf(c[2], c[3]));
#pragma unroll
        for (int off = 16; off > 0; off >>= 1)
            cc = fminf(cc, __shfl_xor_sync(0xFFFFFFFFu, cc, off));
        if (lid == 0) s_cand[t * CSTRIDE + wid] = cc;
    }

    // ---- row-min merges
#pragma unroll
    for (int j = 0; j < QPT; j++)
        atomicMax(&g_key[b * NPTS + q0 + j * THREADS], dkey(rm[j]));

    __syncthreads();

    // ---- col-min: threads 0..63 combine 4 warp candidates for their target
    if (tid < TT) {
        const float* cr = s_cand + tid * CSTRIDE;
        float v = fminf(fminf(cr[0], cr[1]), fminf(cr[2], cr[3]));
        atomicMax(&g_key[COLBASE + b * NPTS + tt * TT + tid], dkey(v));
    }
}

// K2: 8 blocks x 1024 threads: decode+sum 4096 keys each (1 uint4/thread),
// reset keys to 0, ticketed fixed-order final sum by last block.
__global__ __launch_bounds__(R_THREADS)
void chamfer_k2(float* __restrict__ out) {
    __shared__ float s_wsum[R_THREADS / 32];

    const int i = blockIdx.x * R_THREADS + threadIdx.x;   // uint4 index
    uint4* K4 = reinterpret_cast<uint4*>(g_key);
    uint4 k = K4[i];
    K4[i] = make_uint4(0u, 0u, 0u, 0u);                   // restore sentinel
    float v = (key2f(k.x) + key2f(k.y)) + (key2f(k.z) + key2f(k.w));

#pragma unroll
    for (int off = 16; off > 0; off >>= 1)
        v += __shfl_down_sync(0xFFFFFFFFu, v, off);
    if ((threadIdx.x & 31) == 0) s_wsum[threadIdx.x >> 5] = v;
    __syncthreads();

    if (threadIdx.x == 0) {
        float bs = 0.0f;
#pragma unroll
        for (int w = 0; w < R_THREADS / 32; w++) bs += s_wsum[w];
        g_bsum[blockIdx.x] = bs;
        __threadfence();
        unsigned int prev = atomicAdd(&g_count, 1u);
        if (prev == R_NBLK - 1) {       // last block: fixed-order final sum
            __threadfence();
            float tot = 0.0f;
#pragma unroll
            for (int i2 = 0; i2 < R_NBLK; i2++) tot += g_bsum[i2];
            out[0] = tot / (float)(BATCH * NPTS);
            g_count = 0u;               // reset for next graph replay
        }
    }
}

extern "C" void kernel_launch(void* const* d_in, const int* in_sizes, int n_in,
                              void* d_out, int out_size) {
    const float* src = (const float*)d_in[0];  // (B, N, 3)
    const float* tgt = (const float*)d_in[1];  // (B, M, 3)
    float* out = (float*)d_out;

    dim3 grid(NQBLK, NTTILE, BATCH);  // 4 x 64 x 4 = 1024 blocks
    chamfer_k1<<<grid, THREADS>>>(src, tgt);

    chamfer_k2<<<R_NBLK, R_THREADS>>>(out);
}

// round 15
// speedup vs baseline: 1.1786x; 1.1786x over previous
#include <cuda_runtime.h>
#include <math_constants.h>

// Bidirectional Chamfer distance, B=4, N=M=4096, D=3, fp32.
// dist[b,n,m] = |q_n|^2 + |t_m|^2 - 2 q_n.t_m  -- computed ONCE per (n,m),
// serving BOTH directions: row-mins in registers, col-mins via per-step STS
// candidate buffer (R12 scheme; SHFL rejected in R14). QPT=4 / TT=32 gives
// ~45 regs + 18KB smem -> 8 CTAs/SM -> 4096 blocks at <=1.2% wave imbalance.
// Margins merged via atomicMax on monotone keys (0 == +inf sentinel).
// K2: ONE block x 1024 thr: decode+sum+reset keys. Deterministic.

#define BATCH   4
#define NPTS    4096
#define THREADS 128
#define QPT     4
#define QBLK    (THREADS * QPT)          // 512 queries per block
#define NQBLK   (NPTS / QBLK)            // 8
#define TT      32                       // targets per block
#define NTTILE  (NPTS / TT)              // 128
#define NKEY    (2 * BATCH * NPTS)       // 32768: [0,16384) rows, rest cols
#define COLBASE (BATCH * NPTS)           // 16384
#define CSTRIDE (THREADS + 1)            // 129: conflict-free cand stride
#define PSTRIDE (TT + 1)                 // 33: partial stride

#define R_THREADS 1024

__device__ __align__(16) unsigned int g_key[NKEY];  // zero-init == +inf

// key(d) = ~f2key(d): monotone DECREASING in d; all finite d -> key > 0.
__device__ __forceinline__ unsigned int dkey(float f) {
    unsigned int u = __float_as_uint(f);
    unsigned int k = (u & 0x80000000u) ? ~u : (u | 0x80000000u);
    return ~k;
}
__device__ __forceinline__ float key2f(unsigned int kk) {
    unsigned int k = ~kk;
    unsigned int u = (k & 0x80000000u) ? (k & 0x7FFFFFFFu) : ~k;
    return __uint_as_float(u);
}

__global__ __launch_bounds__(THREADS, 8)
void chamfer_k1(const float* __restrict__ src,
                const float* __restrict__ tgt) {
    // sXY[t] = ((-2x,-2x),(-2y,-2y)), sZW[t] = ((-2z,-2z),(w,w)), w=|t|^2
    __shared__ ulonglong2 sXY[TT];
    __shared__ ulonglong2 sZW[TT];
    __shared__ float      s_cand[TT * CSTRIDE];   // [t][thread], 16.5 KB
    __shared__ float      s_part[4 * PSTRIDE];    // [chunk][t]

    const int qblk = blockIdx.x;
    const int tt   = blockIdx.y;
    const int b    = blockIdx.z;
    const int tid  = threadIdx.x;

    const float* __restrict__ qb = src + (size_t)b * NPTS * 3;  // rows: source
    const float* __restrict__ tb = tgt + (size_t)b * NPTS * 3;  // cols: target

    // ---- load + duplicate-pack this block's 32 targets
    if (tid < TT) {
        int m = tt * TT + tid;
        float x = tb[m * 3 + 0], y = tb[m * 3 + 1], z = tb[m * 3 + 2];
        float w = fmaf(x, x, fmaf(y, y, z * z));
        float nx = -2.0f * x, ny = -2.0f * y, nz = -2.0f * z;
        unsigned long long px, py, pz, pw;
        asm("mov.b64 %0, {%1, %1};" : "=l"(px) : "f"(nx));
        asm("mov.b64 %0, {%1, %1};" : "=l"(py) : "f"(ny));
        asm("mov.b64 %0, {%1, %1};" : "=l"(pz) : "f"(nz));
        asm("mov.b64 %0, {%1, %1};" : "=l"(pw) : "f"(w));
        sXY[tid] = make_ulonglong2(px, py);
        sZW[tid] = make_ulonglong2(pz, pw);
    }

    // ---- load 4 queries/thread as 2 f32x2 pairs; |q|^2 packed as chain base
    const int q0 = qblk * QBLK + tid;
    unsigned long long qx2[2], qy2[2], qz2[2], q22[2];
    float rm[QPT];
#pragma unroll
    for (int r = 0; r < 2; r++) {
        int qa = q0 + (2 * r) * THREADS;
        int qc = qa + THREADS;
        float xa = qb[qa * 3 + 0], ya = qb[qa * 3 + 1], za = qb[qa * 3 + 2];
        float xc = qb[qc * 3 + 0], yc = qb[qc * 3 + 1], zc = qb[qc * 3 + 2];
        asm("mov.b64 %0, {%1, %2};" : "=l"(qx2[r]) : "f"(xa), "f"(xc));
        asm("mov.b64 %0, {%1, %2};" : "=l"(qy2[r]) : "f"(ya), "f"(yc));
        asm("mov.b64 %0, {%1, %2};" : "=l"(qz2[r]) : "f"(za), "f"(zc));
        float q2a = fmaf(xa, xa, fmaf(ya, ya, za * za));
        float q2c = fmaf(xc, xc, fmaf(yc, yc, zc * zc));
        asm("mov.b64 %0, {%1, %2};" : "=l"(q22[r]) : "f"(q2a), "f"(q2c));
        rm[2 * r] = CUDART_INF_F;
        rm[2 * r + 1] = CUDART_INF_F;
    }
    __syncthreads();

    // ---- main loop: per step (1 broadcast target x 4 queries):
    //      8 packed fma-ops (fma pipe) + 7 FMNMX (alu) + 1 STS + 2 LDS
#pragma unroll 4
    for (int t = 0; t < TT; t++) {
        ulonglong2 xy = sXY[t];   // .x=(-2x,-2x), .y=(-2y,-2y)
        ulonglong2 zw = sZW[t];   // .x=(-2z,-2z), .y=(w,w)
        float c[2];
#pragma unroll
        for (int r = 0; r < 2; r++) {
            float d0, d1;
            asm("{\n\t"
                ".reg .b64 d;\n\t"
                "fma.rn.f32x2 d, %2, %3, %4;\n\t"   // -2z*qz + |q|^2
                "fma.rn.f32x2 d, %5, %6, d;\n\t"    // -2y*qy
                "fma.rn.f32x2 d, %7, %8, d;\n\t"    // -2x*qx
                "add.rn.f32x2 d, d, %9;\n\t"        // + |t|^2
                "mov.b64 {%0, %1}, d;\n\t"
                "}"
                : "=f"(d0), "=f"(d1)
                : "l"(zw.x), "l"(qz2[r]), "l"(q22[r]),
                  "l"(xy.y), "l"(qy2[r]),
                  "l"(xy.x), "l"(qx2[r]),
                  "l"(zw.y));
            rm[2 * r]     = fminf(rm[2 * r], d0);
            rm[2 * r + 1] = fminf(rm[2 * r + 1], d1);
            c[r] = fminf(d0, d1);
        }
        s_cand[t * CSTRIDE + tid] = fminf(c[0], c[1]);
    }

    // ---- row-min merges
#pragma unroll
    for (int j = 0; j < QPT; j++)
        atomicMax(&g_key[b * NPTS + q0 + j * THREADS], dkey(rm[j]));

    __syncthreads();

    // ---- col-min: all 128 threads: target t = tid&31, chunk = tid>>5
    {
        int t = tid & 31, chunk = tid >> 5;
        const float* cr = s_cand + t * CSTRIDE + chunk * 32;
        float v0 = cr[0], v1 = cr[1], v2 = cr[2], v3 = cr[3];
#pragma unroll
        for (int i = 4; i < 32; i += 4) {
            v0 = fminf(v0, cr[i + 0]);
            v1 = fminf(v1, cr[i + 1]);
            v2 = fminf(v2, cr[i + 2]);
            v3 = fminf(v3, cr[i + 3]);
        }
        s_part[chunk * PSTRIDE + t] = fminf(fminf(v0, v1), fminf(v2, v3));
    }
    __syncthreads();
    if (tid < TT) {
        float v = fminf(fminf(s_part[tid], s_part[PSTRIDE + tid]),
                        fminf(s_part[2 * PSTRIDE + tid], s_part[3 * PSTRIDE + tid]));
        atomicMax(&g_key[COLBASE + b * NPTS + tt * TT + tid], dkey(v));
    }
}

// K2: ONE block x 1024 threads: decode+sum 32768 keys (8 uint4/thread,
// contiguous, MLP 8), reset sentinels, block reduce, write out.
__global__ __launch_bounds__(R_THREADS)
void chamfer_k2(float* __restrict__ out) {
    __shared__ float s_wsum[R_THREADS / 32];

    uint4* K4 = reinterpret_cast<uint4*>(g_key);
    float acc = 0.0f;
#pragma unroll
    for (int r = 0; r < NKEY / 4 / R_THREADS; r++) {   // 8 iterations
        int i = r * R_THREADS + threadIdx.x;
        uint4 k = K4[i];
        K4[i] = make_uint4(0u, 0u, 0u, 0u);            // restore sentinel
        acc += (key2f(k.x) + key2f(k.y)) + (key2f(k.z) + key2f(k.w));
    }

#pragma unroll
    for (int off = 16; off > 0; off >>= 1)
        acc += __shfl_down_sync(0xFFFFFFFFu, acc, off);
    if ((threadIdx.x & 31) == 0) s_wsum[threadIdx.x >> 5] = acc;
    __syncthreads();

    if (threadIdx.x == 0) {
        float tot = 0.0f;
#pragma unroll
        for (int w = 0; w < R_THREADS / 32; w++) tot += s_wsum[w];
        out[0] = tot / (float)(BATCH * NPTS);
    }
}

extern "C" void kernel_launch(void* const* d_in, const int* in_sizes, int n_in,
                              void* d_out, int out_size) {
    const float* src = (const float*)d_in[0];  // (B, N, 3)
    const float* tgt = (const float*)d_in[1];  // (B, M, 3)
    float* out = (float*)d_out;

    dim3 grid(NQBLK, NTTILE, BATCH);  // 8 x 128 x 4 = 4096 blocks
    chamfer_k1<<<grid, THREADS>>>(src, tgt);

    chamfer_k2<<<1, R_THREADS>>>(out);
}

// round 16
// speedup vs baseline: 1.4208x; 1.2056x over previous
#include <cuda_runtime.h>
#include <math_constants.h>

// Bidirectional Chamfer distance, B=4, N=M=4096, D=3, fp32.
// dist[b,n,m] = |q_n|^2 + |t_m|^2 - 2 q_n.t_m  -- computed ONCE per (n,m),
// serving BOTH directions (R12 kernel, measured at the fma-pipe floor).
// Margins merged via atomicMax on monotone keys (0 == +inf sentinel).
// Tail: K2 launched with Programmatic Dependent Launch -- K1 blocks signal
// griddepcontrol.launch_dependents after their fenced merges; K2 CTAs
// pre-launch and griddepcontrol.wait in HW, skipping the serial launch gap.

#define BATCH   4
#define NPTS    4096
#define THREADS 128
#define QPT     8
#define QBLK    (THREADS * QPT)          // 1024 queries per block
#define NQBLK   (NPTS / QBLK)            // 4
#define TT      64                       // targets per block
#define NTTILE  (NPTS / TT)              // 64
#define NKEY    (2 * BATCH * NPTS)       // 32768: [0,16384) rows, rest cols
#define COLBASE (BATCH * NPTS)           // 16384
#define CSTRIDE 129                      // cand row stride (conflict-free)

#define R_THREADS 256
#define R_NBLK    (NKEY / (4 * R_THREADS))   // 32 blocks, 1 uint4/thread

__device__ __align__(16) unsigned int g_key[NKEY];  // zero-init == +inf
__device__ float        g_bsum[R_NBLK];
__device__ unsigned int g_count;                    // zero-init; reset at end

// key(d) = ~f2key(d): monotone DECREASING in d; all finite d -> key > 0.
__device__ __forceinline__ unsigned int dkey(float f) {
    unsigned int u = __float_as_uint(f);
    unsigned int k = (u & 0x80000000u) ? ~u : (u | 0x80000000u);
    return ~k;
}
__device__ __forceinline__ float key2f(unsigned int kk) {
    unsigned int k = ~kk;
    unsigned int u = (k & 0x80000000u) ? (k & 0x7FFFFFFFu) : ~k;
    return __uint_as_float(u);
}

__global__ __launch_bounds__(THREADS)
void chamfer_k1(const float* __restrict__ src,
                const float* __restrict__ tgt) {
    // sXY[t] = ((-2x,-2x),(-2y,-2y)), sZW[t] = ((-2z,-2z),(w,w)), w=|t|^2
    __shared__ ulonglong2 sXY[TT];
    __shared__ ulonglong2 sZW[TT];
    __shared__ float      s_cand[TT * CSTRIDE];  // [t][thread]

    const int qblk = blockIdx.x;
    const int tt   = blockIdx.y;
    const int b    = blockIdx.z;
    const int tid  = threadIdx.x;

    const float* __restrict__ qb = src + (size_t)b * NPTS * 3;  // rows: source
    const float* __restrict__ tb = tgt + (size_t)b * NPTS * 3;  // cols: target

    // ---- load + duplicate-pack this block's 64 targets
    if (tid < TT) {
        int m = tt * TT + tid;
        float x = tb[m * 3 + 0], y = tb[m * 3 + 1], z = tb[m * 3 + 2];
        float w = fmaf(x, x, fmaf(y, y, z * z));
        float nx = -2.0f * x, ny = -2.0f * y, nz = -2.0f * z;
        unsigned long long px, py, pz, pw;
        asm("mov.b64 %0, {%1, %1};" : "=l"(px) : "f"(nx));
        asm("mov.b64 %0, {%1, %1};" : "=l"(py) : "f"(ny));
        asm("mov.b64 %0, {%1, %1};" : "=l"(pz) : "f"(nz));
        asm("mov.b64 %0, {%1, %1};" : "=l"(pw) : "f"(w));
        sXY[tid] = make_ulonglong2(px, py);
        sZW[tid] = make_ulonglong2(pz, pw);
    }

    // ---- load 8 queries/thread as 4 f32x2 pairs; |q|^2 packed as chain base
    const int q0 = qblk * QBLK + tid;
    unsigned long long qx2[4], qy2[4], qz2[4], q22[4];
    float rm[QPT];
#pragma unroll
    for (int r = 0; r < 4; r++) {
        int qa = q0 + (2 * r) * THREADS;
        int qc = qa + THREADS;
        float xa = qb[qa * 3 + 0], ya = qb[qa * 3 + 1], za = qb[qa * 3 + 2];
        float xc = qb[qc * 3 + 0], yc = qb[qc * 3 + 1], zc = qb[qc * 3 + 2];
        asm("mov.b64 %0, {%1, %2};" : "=l"(qx2[r]) : "f"(xa), "f"(xc));
        asm("mov.b64 %0, {%1, %2};" : "=l"(qy2[r]) : "f"(ya), "f"(yc));
        asm("mov.b64 %0, {%1, %2};" : "=l"(qz2[r]) : "f"(za), "f"(zc));
        float q2a = fmaf(xa, xa, fmaf(ya, ya, za * za));
        float q2c = fmaf(xc, xc, fmaf(yc, yc, zc * zc));
        asm("mov.b64 %0, {%1, %2};" : "=l"(q22[r]) : "f"(q2a), "f"(q2c));
        rm[2 * r] = CUDART_INF_F;
        rm[2 * r + 1] = CUDART_INF_F;
    }
    __syncthreads();

    // ---- main loop: per step (1 broadcast target x 8 queries):
    //      16 packed fma-ops + 15 FMNMX (alu) + 1 STS + 2 LDS
#pragma unroll 4
    for (int t = 0; t < TT; t++) {
        ulonglong2 xy = sXY[t];   // .x=(-2x,-2x), .y=(-2y,-2y)
        ulonglong2 zw = sZW[t];   // .x=(-2z,-2z), .y=(w,w)
        float c[4];
#pragma unroll
        for (int r = 0; r < 4; r++) {
            float d0, d1;
            asm("{\n\t"
                ".reg .b64 d;\n\t"
                "fma.rn.f32x2 d, %2, %3, %4;\n\t"   // -2z*qz + |q|^2
                "fma.rn.f32x2 d, %5, %6, d;\n\t"    // -2y*qy
                "fma.rn.f32x2 d, %7, %8, d;\n\t"    // -2x*qx
                "add.rn.f32x2 d, d, %9;\n\t"        // + |t|^2
                "mov.b64 {%0, %1}, d;\n\t"
                "}"
                : "=f"(d0), "=f"(d1)
                : "l"(zw.x), "l"(qz2[r]), "l"(q22[r]),
                  "l"(xy.y), "l"(qy2[r]),
                  "l"(xy.x), "l"(qx2[r]),
                  "l"(zw.y));
            rm[2 * r]     = fminf(rm[2 * r], d0);
            rm[2 * r + 1] = fminf(rm[2 * r + 1], d1);
            c[r] = fminf(d0, d1);
        }
        s_cand[t * CSTRIDE + tid] = fminf(fminf(c[0], c[1]), fminf(c[2], c[3]));
    }

    // ---- row-min merges
#pragma unroll
    for (int j = 0; j < QPT; j++)
        atomicMax(&g_key[b * NPTS + q0 + j * THREADS], dkey(rm[j]));

    __syncthreads();

    // ---- col-min: threads 0..63 reduce 128 candidates for their target
    if (tid < TT) {
        const float* cr = s_cand + tid * CSTRIDE;
        float v0 = cr[0], v1 = cr[1], v2 = cr[2], v3 = cr[3];
#pragma unroll
        for (int i = 4; i < THREADS; i += 4) {
            v0 = fminf(v0, cr[i + 0]);
            v1 = fminf(v1, cr[i + 1]);
            v2 = fminf(v2, cr[i + 2]);
            v3 = fminf(v3, cr[i + 3]);
        }
        float v = fminf(fminf(v0, v1), fminf(v2, v3));
        atomicMax(&g_key[COLBASE + b * NPTS + tt * TT + tid], dkey(v));
    }

    // ---- PDL: this block's merges are done and fenced; allow dependents.
    __threadfence();
    __syncthreads();
    asm volatile("griddepcontrol.launch_dependents;" ::: "memory");
}

// K2 (PDL dependent): wait for K1, then decode+sum 32768 keys
// (1 uint4/thread), reset sentinels, ticketed fixed-order final sum.
__global__ __launch_bounds__(R_THREADS)
void chamfer_k2(float* __restrict__ out) {
    __shared__ float s_wsum[R_THREADS / 32];

    // HW wait: all K1 blocks' pre-launch_dependents writes are visible after.
    asm volatile("griddepcontrol.wait;" ::: "memory");

    const int i = blockIdx.x * R_THREADS + threadIdx.x;   // uint4 index
    uint4* K4 = reinterpret_cast<uint4*>(g_key);
    uint4 k = K4[i];
    K4[i] = make_uint4(0u, 0u, 0u, 0u);                   // restore sentinel
    float v = (key2f(k.x) + key2f(k.y)) + (key2f(k.z) + key2f(k.w));

#pragma unroll
    for (int off = 16; off > 0; off >>= 1)
        v += __shfl_down_sync(0xFFFFFFFFu, v, off);
    if ((threadIdx.x & 31) == 0) s_wsum[threadIdx.x >> 5] = v;
    __syncthreads();

    if (threadIdx.x == 0) {
        float bs = 0.0f;
#pragma unroll
        for (int w = 0; w < R_THREADS / 32; w++) bs += s_wsum[w];
        g_bsum[blockIdx.x] = bs;
        __threadfence();
        unsigned int prev = atomicAdd(&g_count, 1u);
        if (prev == R_NBLK - 1) {       // last block: fixed-order final sum
            __threadfence();
            float tot = 0.0f;
#pragma unroll
            for (int j = 0; j < R_NBLK; j++) tot += g_bsum[j];
            out[0] = tot / (float)(BATCH * NPTS);
            g_count = 0u;               // reset for next graph replay
        }
    }
}

extern "C" void kernel_launch(void* const* d_in, const int* in_sizes, int n_in,
                              void* d_out, int out_size) {
    const float* src = (const float*)d_in[0];  // (B, N, 3)
    const float* tgt = (const float*)d_in[1];  // (B, M, 3)
    float* out = (float*)d_out;

    dim3 grid(NQBLK, NTTILE, BATCH);  // 4 x 64 x 4 = 1024 blocks
    chamfer_k1<<<grid, THREADS>>>(src, tgt);

    // K2 with Programmatic Dependent Launch: pre-launches during K1's drain.
    cudaLaunchConfig_t cfg = {};
    cfg.gridDim  = dim3(R_NBLK);
    cfg.blockDim = dim3(R_THREADS);
    cfg.dynamicSmemBytes = 0;
    cfg.stream = 0;
    cudaLaunchAttribute attr[1];
    attr[0].id = cudaLaunchAttributeProgrammaticStreamSerialization;
    attr[0].val.programmaticStreamSerializationAllowed = 1;
    cfg.attrs = attr;
    cfg.numAttrs = 1;
    cudaLaunchKernelEx(&cfg, chamfer_k2, out);
}